// round 9
// baseline (speedup 1.0000x reference)
#include <cuda_runtime.h>
#include <cuda_bf16.h>
#include <cstdint>
#include <cstddef>

// ---------------------------------------------------------------------------
// Scratch (__device__ globals; no cudaMalloc allowed)
// ---------------------------------------------------------------------------
__device__ float g_c[64];
__device__ __align__(16) __nv_bfloat16 g_Mhi[64 * 1024];
__device__ __align__(16) __nv_bfloat16 g_Mlo[64 * 1024];
__device__ int g_cnt[20];   // [0..15]: chunk counters (target 1024), [16]: c counter (target 64)

#define GRID      148
#define NUM_CHUNK 16
#define CHUNK     64
#define LDA       72
#define AHI_OFF   0
#define ALO_OFF   9216
#define BHI_OFF   18432
#define BLO_OFF   27648
#define STAGE_BYTES 36864
#define SX2_OFF   0
#define ST0       4096
#define RED_OFF   (ST0 + 2 * STAGE_BYTES)          // 77824
#define SMEM_TOTAL (RED_OFF + 512)                  // 78336

// ---------------------------------------------------------------------------
// Sync helpers
// ---------------------------------------------------------------------------
__device__ __forceinline__ int ld_acquire(const int* p) {
    int v;
    asm volatile("ld.acquire.gpu.b32 %0, [%1];" : "=r"(v) : "l"(p) : "memory");
    return v;
}

// Called by ONE consumer warp (warp 0) only; other warps park at WBAR.
__device__ __forceinline__ void wait_cnt(const int* c, int target) {
    if ((threadIdx.x & 31) == 0) {
        while (ld_acquire(c) < target) __nanosleep(64);
    }
    __syncwarp();
}

#define CBAR() asm volatile("bar.sync 1, 256;" ::: "memory")   // consumer stage barrier
#define WBAR() asm volatile("bar.sync 3, 256;" ::: "memory")   // consumer wait-release

__device__ __forceinline__ uint32_t pack_bf16x2(__nv_bfloat16 a, __nv_bfloat16 b) {
    __nv_bfloat162 t; t.x = a; t.y = b;
    return *reinterpret_cast<uint32_t*>(&t);
}

__device__ __forceinline__ void split_pair(float f0, float f1, uint32_t& h, uint32_t& l) {
    __nv_bfloat16 h0 = __float2bfloat16_rn(f0);
    __nv_bfloat16 h1 = __float2bfloat16_rn(f1);
    h = pack_bf16x2(h0, h1);
    l = pack_bf16x2(__float2bfloat16_rn(f0 - __bfloat162float(h0)),
                    __float2bfloat16_rn(f1 - __bfloat162float(h1)));
}

__device__ __forceinline__ void mma16816(float d[4], const uint32_t a[4],
                                         uint32_t b0, uint32_t b1) {
    asm volatile(
        "mma.sync.aligned.m16n8k16.row.col.f32.bf16.bf16.f32 "
        "{%0,%1,%2,%3}, {%4,%5,%6,%7}, {%8,%9}, {%0,%1,%2,%3};"
        : "+f"(d[0]), "+f"(d[1]), "+f"(d[2]), "+f"(d[3])
        : "r"(a[0]), "r"(a[1]), "r"(a[2]), "r"(a[3]), "r"(b0), "r"(b1));
}

// ---------------------------------------------------------------------------
// Consumer pieces (ctid = 0..255); CHUNK=64, BM=64 rows
// ---------------------------------------------------------------------------
__device__ __forceinline__ void ldg_a(const float* __restrict__ x1, int row0, int ch,
                                      int ctid, float4 pa[4]) {
#pragma unroll
    for (int t = 0; t < 4; t++) {
        int g = ctid + t * 256;             // 0..1023
        int r = g >> 4;                     // row 0..63
        int c4 = (g & 15) * 4;              // col 0..60
        pa[t] = *reinterpret_cast<const float4*>(x1 + (size_t)(row0 + r) * 1024 + ch * CHUNK + c4);
    }
}

__device__ __forceinline__ void ldg_b(int ch, int ctid, uint4 pbh[2], uint4 pbl[2]) {
#pragma unroll
    for (int t = 0; t < 2; t++) {
        int g = ctid + t * 256;             // 0..511
        int n = g >> 3;                     // k_out 0..63
        int k8 = (g & 7) * 8;               // col 0..56
        pbh[t] = *reinterpret_cast<const uint4*>(g_Mhi + (size_t)n * 1024 + ch * CHUNK + k8);
        pbl[t] = *reinterpret_cast<const uint4*>(g_Mlo + (size_t)n * 1024 + ch * CHUNK + k8);
    }
}

__device__ __forceinline__ void sts_chunk(char* stage, int ctid, const float4 pa[4],
                                          const uint4 pbh[2], const uint4 pbl[2]) {
#pragma unroll
    for (int t = 0; t < 4; t++) {
        int g = ctid + t * 256;
        int r = g >> 4;
        int c4 = (g & 15) * 4;
        uint32_t h0, l0, h1, l1;
        split_pair(pa[t].x, pa[t].y, h0, l0);
        split_pair(pa[t].z, pa[t].w, h1, l1);
        int off = (r * LDA + c4) * 2;
        *reinterpret_cast<uint2*>(stage + AHI_OFF + off) = make_uint2(h0, h1);
        *reinterpret_cast<uint2*>(stage + ALO_OFF + off) = make_uint2(l0, l1);
    }
#pragma unroll
    for (int t = 0; t < 2; t++) {
        int g = ctid + t * 256;
        int n = g >> 3;
        int k8 = (g & 7) * 8;
        int off = (n * LDA + k8) * 2;       // multiple of 16 -> uint4 OK
        *reinterpret_cast<uint4*>(stage + BHI_OFF + off) = pbh[t];
        *reinterpret_cast<uint4*>(stage + BLO_OFF + off) = pbl[t];
    }
}

__device__ __forceinline__ void compute_chunk(const char* stage, int m0, int nb,
                                              int lane, float d[4][4]) {
    const __nv_bfloat16* Ah = reinterpret_cast<const __nv_bfloat16*>(stage + AHI_OFF);
    const __nv_bfloat16* Al = reinterpret_cast<const __nv_bfloat16*>(stage + ALO_OFF);
    const __nv_bfloat16* Bh = reinterpret_cast<const __nv_bfloat16*>(stage + BHI_OFF);
    const __nv_bfloat16* Bl = reinterpret_cast<const __nv_bfloat16*>(stage + BLO_OFF);
    int g = lane >> 2, tg2 = (lane & 3) * 2;
#pragma unroll
    for (int ks = 0; ks < CHUNK / 16; ks++) {
        int k0 = ks * 16;
        int abase = (m0 + g) * LDA + k0 + tg2;
        uint32_t ah[4], al[4];
        ah[0] = *reinterpret_cast<const uint32_t*>(Ah + abase);
        ah[1] = *reinterpret_cast<const uint32_t*>(Ah + abase + 8 * LDA);
        ah[2] = *reinterpret_cast<const uint32_t*>(Ah + abase + 8);
        ah[3] = *reinterpret_cast<const uint32_t*>(Ah + abase + 8 * LDA + 8);
        al[0] = *reinterpret_cast<const uint32_t*>(Al + abase);
        al[1] = *reinterpret_cast<const uint32_t*>(Al + abase + 8 * LDA);
        al[2] = *reinterpret_cast<const uint32_t*>(Al + abase + 8);
        al[3] = *reinterpret_cast<const uint32_t*>(Al + abase + 8 * LDA + 8);
#pragma unroll
        for (int j = 0; j < 4; j++) {
            int bbase = (nb + j * 8 + g) * LDA + k0 + tg2;
            uint32_t bh0 = *reinterpret_cast<const uint32_t*>(Bh + bbase);
            uint32_t bh1 = *reinterpret_cast<const uint32_t*>(Bh + bbase + 8);
            uint32_t bl0 = *reinterpret_cast<const uint32_t*>(Bl + bbase);
            uint32_t bl1 = *reinterpret_cast<const uint32_t*>(Bl + bbase + 8);
            mma16816(d[j], ah, bh0, bh1);
            mma16816(d[j], ah, bl0, bl1);
            mma16816(d[j], al, bh0, bh1);
        }
    }
}

// ---------------------------------------------------------------------------
// Fused persistent kernel: 148 CTAs x 512 threads (one wave, deadlock-safe).
//   warps 8-15 (hi-wid): producers — 1024 active producer warps over 148 SMs,
//                        each owns (k, 4-d quad) per chunk; barrier-free signal
//   warps 0-7 (lo-wid), CTAs < 128: consumers — HMMA GEMM + fused epilogue
// ---------------------------------------------------------------------------
__global__ __launch_bounds__(512, 1) void fused_kernel(const float* __restrict__ W,
                                                       const float* __restrict__ V,
                                                       const float* __restrict__ x2,
                                                       const float* __restrict__ b,
                                                       const float* __restrict__ x1,
                                                       const float* __restrict__ U,
                                                       float* __restrict__ out) {
    extern __shared__ char smem[];
    float* sx2 = reinterpret_cast<float*>(smem + SX2_OFF);
    int tid = threadIdx.x, lane = tid & 31, wid = tid >> 5;

    if (tid < 256) {
        reinterpret_cast<float4*>(sx2)[tid] = reinterpret_cast<const float4*>(x2)[tid];
    }
    __syncthreads();   // only block-wide sync; roles diverge after this

    if (wid >= 8) {
        // ========== PRODUCERS (hi-wid; no barriers; 1024 active of 1184) ==========
        int q = blockIdx.x * 8 + (wid - 8);     // 0..1183
        const float4* xx = reinterpret_cast<const float4*>(sx2);

        if (q < 64) {
            // c[q] = b[q] + V2[q]·x2
            const float4* v = reinterpret_cast<const float4*>(V + (size_t)q * 2048 + 1024);
            float s = 0.0f;
#pragma unroll
            for (int j = 0; j < 8; j++) {
                float4 a = v[lane + j * 32];
                float4 x = xx[lane + j * 32];
                s += a.x * x.x + a.y * x.y + a.z * x.z + a.w * x.w;
            }
#pragma unroll
            for (int o = 16; o; o >>= 1) s += __shfl_xor_sync(0xFFFFFFFFu, s, o);
            if (lane == 0) {
                g_c[q] = s + b[q];
                __threadfence();
                atomicAdd(&g_cnt[16], 1);       // target 64
            }
        }

        if (q < 1024) {
            int k = q >> 4;                     // 0..63
            int quad = q & 15;                  // 4-d group within chunk
            for (int ch = 0; ch < NUM_CHUNK; ch++) {
                int dbase = ch * CHUNK + quad * 4;
#pragma unroll 1
                for (int i = 0; i < 4; i += 2) {
                    int d0 = dbase + i;
                    const float4* w0 = reinterpret_cast<const float4*>(W + ((size_t)k * 1024 + d0) * 1024);
                    const float4* w1 = reinterpret_cast<const float4*>(W + ((size_t)k * 1024 + d0 + 1) * 1024);
                    // 2 accumulator chains per row: halves the serial FMA depth
                    float s0a = 0.f, s0b = 0.f, s1a = 0.f, s1b = 0.f;
#pragma unroll
                    for (int j = 0; j < 4; j++) {
                        float4 a0 = __ldcs(&w0[lane + j * 32]);
                        float4 b0 = __ldcs(&w0[lane + (j + 4) * 32]);
                        float4 a1 = __ldcs(&w1[lane + j * 32]);
                        float4 b1 = __ldcs(&w1[lane + (j + 4) * 32]);
                        float4 xa = xx[lane + j * 32];
                        float4 xb = xx[lane + (j + 4) * 32];
                        s0a += a0.x * xa.x + a0.y * xa.y + a0.z * xa.z + a0.w * xa.w;
                        s0b += b0.x * xb.x + b0.y * xb.y + b0.z * xb.z + b0.w * xb.w;
                        s1a += a1.x * xa.x + a1.y * xa.y + a1.z * xa.z + a1.w * xa.w;
                        s1b += b1.x * xb.x + b1.y * xb.y + b1.z * xb.z + b1.w * xb.w;
                    }
                    float s0 = s0a + s0b, s1 = s1a + s1b;
#pragma unroll
                    for (int o = 16; o; o >>= 1) {
                        s0 += __shfl_xor_sync(0xFFFFFFFFu, s0, o);
                        s1 += __shfl_xor_sync(0xFFFFFFFFu, s1, o);
                    }
                    if (lane == 0) {
                        float m0v = s0 + V[(size_t)k * 2048 + d0];
                        float m1v = s1 + V[(size_t)k * 2048 + d0 + 1];
                        __nv_bfloat16 h0 = __float2bfloat16_rn(m0v);
                        __nv_bfloat16 h1 = __float2bfloat16_rn(m1v);
                        size_t mi = (size_t)k * 1024 + d0;
                        g_Mhi[mi] = h0;
                        g_Mhi[mi + 1] = h1;
                        g_Mlo[mi] = __float2bfloat16_rn(m0v - __bfloat162float(h0));
                        g_Mlo[mi + 1] = __float2bfloat16_rn(m1v - __bfloat162float(h1));
                    }
                }
                if (lane == 0) {
                    __threadfence();
                    atomicAdd(&g_cnt[ch], 1);   // target 1024
                }
            }
        }
    } else if (blockIdx.x < 128) {
        // ================= CONSUMERS (lo-wid, first 128 CTAs) =================
        int ctid = tid;                         // 0..255
        int cw = ctid >> 5;                     // 0..7
        int wr = cw & 3, wc = cw >> 2;
        int m0 = wr * 16, nb = wc * 32;
        int row0 = blockIdx.x * 64;
        float* red = reinterpret_cast<float*>(smem + RED_OFF);

        float d[4][4] = {};
        float4 pa[4];
        uint4 pbh[2], pbl[2];

        ldg_a(x1, row0, 0, ctid, pa);
        if (cw == 0) wait_cnt(&g_cnt[0], 1024);
        WBAR();
        ldg_b(0, ctid, pbh, pbl);
        sts_chunk(smem + ST0, ctid, pa, pbh, pbl);
        CBAR();

        for (int ch = 0; ch < NUM_CHUNK; ch++) {
            compute_chunk(smem + ST0 + (ch & 1) * STAGE_BYTES, m0, nb, lane, d);
            if (ch < NUM_CHUNK - 1) {
                ldg_a(x1, row0, ch + 1, ctid, pa);
                if (cw == 0) wait_cnt(&g_cnt[ch + 1], 1024);
                WBAR();
                ldg_b(ch + 1, ctid, pbh, pbl);
                sts_chunk(smem + ST0 + ((ch + 1) & 1) * STAGE_BYTES, ctid, pa, pbh, pbl);
                CBAR();
            }
        }

        // fused epilogue: relu(D + c)*U, row-reduce over 64 cols -> out (N,1)
        if (cw == 0) wait_cnt(&g_cnt[16], 64);
        WBAR();
        int g = lane >> 2, tg2 = (lane & 3) * 2;
        float accA = 0.0f, accB = 0.0f;
#pragma unroll
        for (int j = 0; j < 4; j++) {
            int col = nb + j * 8 + tg2;
            float c0 = g_c[col], c1 = g_c[col + 1];
            float u0 = U[col], u1 = U[col + 1];
            accA += fmaxf(d[j][0] + c0, 0.0f) * u0 + fmaxf(d[j][1] + c1, 0.0f) * u1;
            accB += fmaxf(d[j][2] + c0, 0.0f) * u0 + fmaxf(d[j][3] + c1, 0.0f) * u1;
        }
        accA += __shfl_xor_sync(0xFFFFFFFFu, accA, 1);
        accA += __shfl_xor_sync(0xFFFFFFFFu, accA, 2);
        accB += __shfl_xor_sync(0xFFFFFFFFu, accB, 1);
        accB += __shfl_xor_sync(0xFFFFFFFFu, accB, 2);
        if ((lane & 3) == 0) {
            red[wc * 64 + m0 + g] = accA;
            red[wc * 64 + m0 + 8 + g] = accB;
        }
        CBAR();
        if (ctid < 64) out[row0 + ctid] = red[ctid] + red[64 + ctid];
    }
}

// ---------------------------------------------------------------------------
extern "C" void kernel_launch(void* const* d_in, const int* in_sizes, int n_in,
                              void* d_out, int out_size) {
    const float* x1 = (const float*)d_in[0];  // (8192, 1024)
    const float* x2 = (const float*)d_in[1];  // (1, 1024)
    const float* V  = (const float*)d_in[2];  // (64, 2048)
    const float* W  = (const float*)d_in[3];  // (64, 1024, 1024)
    const float* b  = (const float*)d_in[4];  // (64,)
    const float* U  = (const float*)d_in[5];  // (64, 1)
    float* out = (float*)d_out;               // (8192, 1)

    // zero counters each launch (graph-capturable, no allocation)
    void* cnt_addr = nullptr;
    cudaGetSymbolAddress(&cnt_addr, g_cnt);
    cudaMemsetAsync(cnt_addr, 0, sizeof(int) * 20, 0);

    cudaFuncSetAttribute(fused_kernel, cudaFuncAttributeMaxDynamicSharedMemorySize, SMEM_TOTAL);
    fused_kernel<<<GRID, 512, SMEM_TOTAL>>>(W, V, x2, b, x1, U, out);
}

// round 10
// speedup vs baseline: 1.0530x; 1.0530x over previous
#include <cuda_runtime.h>
#include <cuda_bf16.h>
#include <cstdint>
#include <cstddef>

// ---------------------------------------------------------------------------
// Scratch (__device__ globals; no cudaMalloc allowed)
// ---------------------------------------------------------------------------
__device__ float g_c[64];
__device__ __align__(16) __nv_bfloat16 g_Mhi[64 * 1024];
__device__ __align__(16) __nv_bfloat16 g_Mlo[64 * 1024];

// ---------------------------------------------------------------------------
// Kernel A (fused): blocks [0,8192): M[k,d] = V[k,d] + sum_e W[k,d,e]*x2[e]
//                   blocks [8192,8256): c[k] = b[k] + V2[k]·x2
// One warp per (k,d) pair; streams 256 MB of W once (HBM-bound, ~82% DRAM).
// ---------------------------------------------------------------------------
__global__ __launch_bounds__(256) void wx2_kernel(const float* __restrict__ W,
                                                  const float* __restrict__ V,
                                                  const float* __restrict__ x2,
                                                  const float* __restrict__ b) {
    if (blockIdx.x >= 8192) {
        int k = blockIdx.x - 8192;
        if (threadIdx.x < 32) {
            int lane = threadIdx.x;
            const float4* v = reinterpret_cast<const float4*>(V + (size_t)k * 2048 + 1024);
            const float4* xx = reinterpret_cast<const float4*>(x2);
            float s = 0.0f;
#pragma unroll
            for (int i = 0; i < 8; i++) {
                float4 a = v[lane + i * 32];
                float4 c = xx[lane + i * 32];
                s += a.x * c.x + a.y * c.y + a.z * c.z + a.w * c.w;
            }
#pragma unroll
            for (int o = 16; o; o >>= 1) s += __shfl_xor_sync(0xFFFFFFFFu, s, o);
            if (lane == 0) g_c[k] = s + b[k];
        }
        return;
    }

    __shared__ float sx2[1024];
    {
        const float4* src = reinterpret_cast<const float4*>(x2);
        float4* dst = reinterpret_cast<float4*>(sx2);
        dst[threadIdx.x] = src[threadIdx.x];
    }
    __syncthreads();

    int pair = blockIdx.x * 8 + (threadIdx.x >> 5);
    int lane = threadIdx.x & 31;
    int k = pair >> 10;
    int d = pair & 1023;

    const float4* w = reinterpret_cast<const float4*>(W + (size_t)pair * 1024);
    const float4* xx = reinterpret_cast<const float4*>(sx2);

    float s = 0.0f;
#pragma unroll
    for (int i = 0; i < 8; i++) {
        float4 wv = __ldcs(&w[lane + i * 32]);   // streaming: W touched exactly once
        float4 xv = xx[lane + i * 32];
        s += wv.x * xv.x + wv.y * xv.y + wv.z * xv.z + wv.w * xv.w;
    }
#pragma unroll
    for (int o = 16; o; o >>= 1) s += __shfl_xor_sync(0xFFFFFFFFu, s, o);

    if (lane == 0) {
        float m = s + V[(size_t)k * 2048 + d];
        __nv_bfloat16 hi = __float2bfloat16_rn(m);
        __nv_bfloat16 lo = __float2bfloat16_rn(m - __bfloat162float(hi));
        g_Mhi[pair] = hi;
        g_Mlo[pair] = lo;
    }
}

// ---------------------------------------------------------------------------
// Kernel B: mma.sync split-bf16 GEMM + fused relu/U epilogue.
// out[n] = sum_k relu((x1 @ M^T)[n,k] + c[k]) * U[k]
// Grid 256 CTAs (BM=32 rows), 256 thr (8 warps, 2x4), 2 CTAs/SM.
// Warp tile 16m x 16n. D in 8 chunks of 128. B tiles via cp.async (M is
// L2-resident so the 2x duplication is free at DRAM). A: LDG->split->STS.
// ---------------------------------------------------------------------------
#define BM        32
#define CHUNK     128
#define LDA       136
#define A_HI      0
#define A_LO      8704
#define B_HI      17408
#define B_LO      34816
#define STAGE_BYTES 52224
#define C_OFF     (2 * STAGE_BYTES)      // 104448
#define U_OFF     (C_OFF + 256)
#define RED_OFF   (U_OFF + 256)
#define SMEM_TOTAL (RED_OFF + 512)       // 105472

__device__ __forceinline__ uint32_t smem_u32(const void* p) {
    return (uint32_t)__cvta_generic_to_shared(p);
}

#define CP_ASYNC16(dst_u32, src_ptr) \
    asm volatile("cp.async.cg.shared.global [%0], [%1], 16;" :: "r"(dst_u32), "l"(src_ptr))
#define CP_COMMIT() asm volatile("cp.async.commit_group;" ::: "memory")
#define CP_WAIT0()  asm volatile("cp.async.wait_group 0;" ::: "memory")

__device__ __forceinline__ uint32_t pack_bf16x2(__nv_bfloat16 a, __nv_bfloat16 b) {
    __nv_bfloat162 t; t.x = a; t.y = b;
    return *reinterpret_cast<uint32_t*>(&t);
}

__device__ __forceinline__ void split_pair(float f0, float f1, uint32_t& h, uint32_t& l) {
    __nv_bfloat16 h0 = __float2bfloat16_rn(f0);
    __nv_bfloat16 h1 = __float2bfloat16_rn(f1);
    h = pack_bf16x2(h0, h1);
    l = pack_bf16x2(__float2bfloat16_rn(f0 - __bfloat162float(h0)),
                    __float2bfloat16_rn(f1 - __bfloat162float(h1)));
}

__device__ __forceinline__ void mma16816(float d[4], const uint32_t a[4],
                                         uint32_t b0, uint32_t b1) {
    asm volatile(
        "mma.sync.aligned.m16n8k16.row.col.f32.bf16.bf16.f32 "
        "{%0,%1,%2,%3}, {%4,%5,%6,%7}, {%8,%9}, {%0,%1,%2,%3};"
        : "+f"(d[0]), "+f"(d[1]), "+f"(d[2]), "+f"(d[3])
        : "r"(a[0]), "r"(a[1]), "r"(a[2]), "r"(a[3]), "r"(b0), "r"(b1));
}

// A chunk: 32 rows x 128 fp32 = 1024 float4; 4 per thread
__device__ __forceinline__ void ldg_a(const float* __restrict__ x1, int row0, int ch,
                                      int tid, float4 pa[4]) {
#pragma unroll
    for (int t = 0; t < 4; t++) {
        int g = tid + t * 256;              // 0..1023
        int r = g >> 5;                     // row 0..31
        int c4 = (g & 31) * 4;              // col 0..124
        pa[t] = *reinterpret_cast<const float4*>(x1 + (size_t)(row0 + r) * 1024 + ch * CHUNK + c4);
    }
}

// B chunk via cp.async: hi + lo, each 64 rows x 16 x 16B units
__device__ __forceinline__ void cpasync_b(char* stage, int ch, int tid) {
    uint32_t sh = smem_u32(stage + B_HI);
    uint32_t sl = smem_u32(stage + B_LO);
#pragma unroll
    for (int t = 0; t < 4; t++) {
        int g = tid + t * 256;              // 0..1023
        int n = g >> 4;                     // k_out 0..63
        int u = g & 15;                     // 16B unit 0..15
        uint32_t doff = (uint32_t)(n * (LDA * 2) + u * 16);
        const __nv_bfloat16* srch = g_Mhi + (size_t)n * 1024 + ch * CHUNK + u * 8;
        const __nv_bfloat16* srcl = g_Mlo + (size_t)n * 1024 + ch * CHUNK + u * 8;
        CP_ASYNC16(sh + doff, srch);
        CP_ASYNC16(sl + doff, srcl);
    }
}

__device__ __forceinline__ void sts_a(char* stage, int tid, const float4 pa[4]) {
#pragma unroll
    for (int t = 0; t < 4; t++) {
        int g = tid + t * 256;
        int r = g >> 5;
        int c4 = (g & 31) * 4;
        uint32_t h0, l0, h1, l1;
        split_pair(pa[t].x, pa[t].y, h0, l0);
        split_pair(pa[t].z, pa[t].w, h1, l1);
        int off = (r * LDA + c4) * 2;
        *reinterpret_cast<uint2*>(stage + A_HI + off) = make_uint2(h0, h1);
        *reinterpret_cast<uint2*>(stage + A_LO + off) = make_uint2(l0, l1);
    }
}

// Warp tile: 16 rows (m0) x 16 cols (nb), acc d[2][4]
__device__ __forceinline__ void compute_chunk(const char* stage, int m0, int nb,
                                              int lane, float d[2][4]) {
    const __nv_bfloat16* Ah = reinterpret_cast<const __nv_bfloat16*>(stage + A_HI);
    const __nv_bfloat16* Al = reinterpret_cast<const __nv_bfloat16*>(stage + A_LO);
    const __nv_bfloat16* Bh = reinterpret_cast<const __nv_bfloat16*>(stage + B_HI);
    const __nv_bfloat16* Bl = reinterpret_cast<const __nv_bfloat16*>(stage + B_LO);
    int g = lane >> 2, tg2 = (lane & 3) * 2;
#pragma unroll
    for (int ks = 0; ks < CHUNK / 16; ks++) {
        int k0 = ks * 16;
        int abase = (m0 + g) * LDA + k0 + tg2;
        uint32_t ah[4], al[4];
        ah[0] = *reinterpret_cast<const uint32_t*>(Ah + abase);
        ah[1] = *reinterpret_cast<const uint32_t*>(Ah + abase + 8 * LDA);
        ah[2] = *reinterpret_cast<const uint32_t*>(Ah + abase + 8);
        ah[3] = *reinterpret_cast<const uint32_t*>(Ah + abase + 8 * LDA + 8);
        al[0] = *reinterpret_cast<const uint32_t*>(Al + abase);
        al[1] = *reinterpret_cast<const uint32_t*>(Al + abase + 8 * LDA);
        al[2] = *reinterpret_cast<const uint32_t*>(Al + abase + 8);
        al[3] = *reinterpret_cast<const uint32_t*>(Al + abase + 8 * LDA + 8);
#pragma unroll
        for (int nt = 0; nt < 2; nt++) {
            int bbase = (nb + nt * 8 + g) * LDA + k0 + tg2;
            uint32_t bh0 = *reinterpret_cast<const uint32_t*>(Bh + bbase);
            uint32_t bh1 = *reinterpret_cast<const uint32_t*>(Bh + bbase + 8);
            uint32_t bl0 = *reinterpret_cast<const uint32_t*>(Bl + bbase);
            uint32_t bl1 = *reinterpret_cast<const uint32_t*>(Bl + bbase + 8);
            mma16816(d[nt], ah, bh0, bh1);
            mma16816(d[nt], ah, bl0, bl1);
            mma16816(d[nt], al, bh0, bh1);
        }
    }
}

__global__ __launch_bounds__(256, 2) void gemm_mma(const float* __restrict__ x1,
                                                   const float* __restrict__ U,
                                                   float* __restrict__ out) {
    extern __shared__ char smem[];
    int tid = threadIdx.x, lane = tid & 31, wid = tid >> 5;
    int wr = wid & 1, wc = wid >> 1;        // 2x4 warp grid
    int m0 = wr * 16, nb = wc * 16;
    int row0 = blockIdx.x * BM;

    float* sc = reinterpret_cast<float*>(smem + C_OFF);
    float* su = reinterpret_cast<float*>(smem + U_OFF);
    float* red = reinterpret_cast<float*>(smem + RED_OFF);
    if (tid < 64) {
        sc[tid] = g_c[tid];
        su[tid] = U[tid];
    }

    float d[2][4] = {};
    float4 pa[4];

    ldg_a(x1, row0, 0, tid, pa);
    cpasync_b(smem, 0, tid);
    CP_COMMIT();
    sts_a(smem, tid, pa);
    CP_WAIT0();
    __syncthreads();

    for (int ch = 0; ch < 8; ch++) {
        char* cur = smem + (ch & 1) * STAGE_BYTES;
        char* nxt = smem + ((ch + 1) & 1) * STAGE_BYTES;
        if (ch < 7) {
            ldg_a(x1, row0, ch + 1, tid, pa);
            cpasync_b(nxt, ch + 1, tid);
            CP_COMMIT();
        }
        compute_chunk(cur, m0, nb, lane, d);
        if (ch < 7) {
            sts_a(nxt, tid, pa);
            CP_WAIT0();
            __syncthreads();
        }
    }

    // fused epilogue: relu(D + c)*U, row-reduce over this warp's 16 cols
    int g = lane >> 2, tg2 = (lane & 3) * 2;
    float accA = 0.0f, accB = 0.0f;
#pragma unroll
    for (int nt = 0; nt < 2; nt++) {
        int col = nb + nt * 8 + tg2;
        float c0 = sc[col], c1 = sc[col + 1];
        float u0 = su[col], u1 = su[col + 1];
        accA += fmaxf(d[nt][0] + c0, 0.0f) * u0 + fmaxf(d[nt][1] + c1, 0.0f) * u1;
        accB += fmaxf(d[nt][2] + c0, 0.0f) * u0 + fmaxf(d[nt][3] + c1, 0.0f) * u1;
    }
    accA += __shfl_xor_sync(0xFFFFFFFFu, accA, 1);
    accA += __shfl_xor_sync(0xFFFFFFFFu, accA, 2);
    accB += __shfl_xor_sync(0xFFFFFFFFu, accB, 1);
    accB += __shfl_xor_sync(0xFFFFFFFFu, accB, 2);
    if ((lane & 3) == 0) {
        red[wc * 32 + m0 + g] = accA;
        red[wc * 32 + m0 + 8 + g] = accB;
    }
    __syncthreads();
    if (tid < BM) {
        out[row0 + tid] = (red[tid] + red[32 + tid]) + (red[64 + tid] + red[96 + tid]);
    }
}

// ---------------------------------------------------------------------------
extern "C" void kernel_launch(void* const* d_in, const int* in_sizes, int n_in,
                              void* d_out, int out_size) {
    const float* x1 = (const float*)d_in[0];  // (8192, 1024)
    const float* x2 = (const float*)d_in[1];  // (1, 1024)
    const float* V  = (const float*)d_in[2];  // (64, 2048)
    const float* W  = (const float*)d_in[3];  // (64, 1024, 1024)
    const float* b  = (const float*)d_in[4];  // (64,)
    const float* U  = (const float*)d_in[5];  // (64, 1)
    float* out = (float*)d_out;               // (8192, 1)

    cudaFuncSetAttribute(gemm_mma, cudaFuncAttributeMaxDynamicSharedMemorySize, SMEM_TOTAL);

    wx2_kernel<<<8192 + 64, 256>>>(W, V, x2, b);     // HBM-bound + fused c blocks
    gemm_mma<<<256, 256, SMEM_TOTAL>>>(x1, U, out);  // 2 CTA/SM HMMA GEMM + epilogue
}

// round 11
// speedup vs baseline: 1.1238x; 1.0673x over previous
#include <cuda_runtime.h>
#include <cuda_bf16.h>
#include <cstdint>
#include <cstddef>

// ---------------------------------------------------------------------------
// Scratch (__device__ globals; no cudaMalloc allowed)
// ---------------------------------------------------------------------------
__device__ float g_c[64];
__device__ __align__(16) __nv_bfloat16 g_Mhi[64 * 1024];
__device__ __align__(16) __nv_bfloat16 g_Mlo[64 * 1024];

// ---------------------------------------------------------------------------
// Kernel A (fused): blocks [0,8192): M[k,d] = V[k,d] + sum_e W[k,d,e]*x2[e]
//                   blocks [8192,8256): c[k] = b[k] + V2[k]·x2
// One warp per (k,d) pair; streams 256 MB of W once (HBM-bound, ~82% DRAM).
// ---------------------------------------------------------------------------
__global__ __launch_bounds__(256) void wx2_kernel(const float* __restrict__ W,
                                                  const float* __restrict__ V,
                                                  const float* __restrict__ x2,
                                                  const float* __restrict__ b) {
    if (blockIdx.x >= 8192) {
        int k = blockIdx.x - 8192;
        if (threadIdx.x < 32) {
            int lane = threadIdx.x;
            const float4* v = reinterpret_cast<const float4*>(V + (size_t)k * 2048 + 1024);
            const float4* xx = reinterpret_cast<const float4*>(x2);
            float s = 0.0f;
#pragma unroll
            for (int i = 0; i < 8; i++) {
                float4 a = v[lane + i * 32];
                float4 c = xx[lane + i * 32];
                s += a.x * c.x + a.y * c.y + a.z * c.z + a.w * c.w;
            }
#pragma unroll
            for (int o = 16; o; o >>= 1) s += __shfl_xor_sync(0xFFFFFFFFu, s, o);
            if (lane == 0) g_c[k] = s + b[k];
        }
        return;
    }

    __shared__ float sx2[1024];
    {
        const float4* src = reinterpret_cast<const float4*>(x2);
        float4* dst = reinterpret_cast<float4*>(sx2);
        dst[threadIdx.x] = src[threadIdx.x];
    }
    __syncthreads();

    int pair = blockIdx.x * 8 + (threadIdx.x >> 5);
    int lane = threadIdx.x & 31;
    int k = pair >> 10;
    int d = pair & 1023;

    const float4* w = reinterpret_cast<const float4*>(W + (size_t)pair * 1024);
    const float4* xx = reinterpret_cast<const float4*>(sx2);

    float s = 0.0f;
#pragma unroll
    for (int i = 0; i < 8; i++) {
        float4 wv = __ldcs(&w[lane + i * 32]);   // streaming: W touched exactly once
        float4 xv = xx[lane + i * 32];
        s += wv.x * xv.x + wv.y * xv.y + wv.z * xv.z + wv.w * xv.w;
    }
#pragma unroll
    for (int o = 16; o; o >>= 1) s += __shfl_xor_sync(0xFFFFFFFFu, s, o);

    if (lane == 0) {
        float m = s + V[(size_t)k * 2048 + d];
        __nv_bfloat16 hi = __float2bfloat16_rn(m);
        __nv_bfloat16 lo = __float2bfloat16_rn(m - __bfloat162float(hi));
        g_Mhi[pair] = hi;
        g_Mlo[pair] = lo;
    }
}

// ---------------------------------------------------------------------------
// Kernel B: mma.sync split-bf16 GEMM + fused relu/U epilogue.
// out[n] = sum_k relu((x1 @ M^T)[n,k] + c[k]) * U[k]
// Grid 128 CTAs (BM=64), 256 thr (8 warps as 4x2), 1 CTA/SM.
// Fragments via ldmatrix.x4 (48 LDSM vs 192 LDS.32 per warp-chunk);
// B tiles via cp.async (bf16 in gmem, no register trip); A via LDG->split->STS.
// ---------------------------------------------------------------------------
#define CHUNK     128
#define LDA       136
#define A_HI      0
#define A_LO      17408
#define B_HI      34816
#define B_LO      52224
#define STAGE_BYTES 69632
#define C_OFF     (2 * STAGE_BYTES)      // 139264
#define U_OFF     (C_OFF + 256)
#define RED_OFF   (U_OFF + 256)
#define SMEM_TOTAL (RED_OFF + 512)       // 140288

__device__ __forceinline__ uint32_t smem_u32(const void* p) {
    return (uint32_t)__cvta_generic_to_shared(p);
}

#define CP_ASYNC16(dst_u32, src_ptr) \
    asm volatile("cp.async.cg.shared.global [%0], [%1], 16;" :: "r"(dst_u32), "l"(src_ptr))
#define CP_COMMIT() asm volatile("cp.async.commit_group;" ::: "memory")
#define CP_WAIT0()  asm volatile("cp.async.wait_group 0;" ::: "memory")

#define LDSM4(r0, r1, r2, r3, addr) \
    asm volatile("ldmatrix.sync.aligned.m8n8.x4.shared.b16 {%0,%1,%2,%3}, [%4];" \
                 : "=r"(r0), "=r"(r1), "=r"(r2), "=r"(r3) : "r"(addr))

__device__ __forceinline__ uint32_t pack_bf16x2(__nv_bfloat16 a, __nv_bfloat16 b) {
    __nv_bfloat162 t; t.x = a; t.y = b;
    return *reinterpret_cast<uint32_t*>(&t);
}

__device__ __forceinline__ void split_pair(float f0, float f1, uint32_t& h, uint32_t& l) {
    __nv_bfloat16 h0 = __float2bfloat16_rn(f0);
    __nv_bfloat16 h1 = __float2bfloat16_rn(f1);
    h = pack_bf16x2(h0, h1);
    l = pack_bf16x2(__float2bfloat16_rn(f0 - __bfloat162float(h0)),
                    __float2bfloat16_rn(f1 - __bfloat162float(h1)));
}

__device__ __forceinline__ void mma16816(float d[4], const uint32_t a[4],
                                         uint32_t b0, uint32_t b1) {
    asm volatile(
        "mma.sync.aligned.m16n8k16.row.col.f32.bf16.bf16.f32 "
        "{%0,%1,%2,%3}, {%4,%5,%6,%7}, {%8,%9}, {%0,%1,%2,%3};"
        : "+f"(d[0]), "+f"(d[1]), "+f"(d[2]), "+f"(d[3])
        : "r"(a[0]), "r"(a[1]), "r"(a[2]), "r"(a[3]), "r"(b0), "r"(b1));
}

// A chunk: 64 rows x 128 fp32 = 2048 float4; 8 per thread
__device__ __forceinline__ void ldg_a(const float* __restrict__ x1, int row0, int ch,
                                      int tid, float4 pa[8]) {
#pragma unroll
    for (int t = 0; t < 8; t++) {
        int g = tid + t * 256;              // 0..2047
        int r = g >> 5;                     // row 0..63
        int c4 = (g & 31) * 4;              // col 0..124
        pa[t] = *reinterpret_cast<const float4*>(x1 + (size_t)(row0 + r) * 1024 + ch * CHUNK + c4);
    }
}

// B chunk via cp.async: hi + lo, 64 rows x 16 x 16B units each; 8 cp/thread
__device__ __forceinline__ void cpasync_b(char* stage, int ch, int tid) {
    uint32_t sh = smem_u32(stage + B_HI);
    uint32_t sl = smem_u32(stage + B_LO);
#pragma unroll
    for (int t = 0; t < 4; t++) {
        int g = tid + t * 256;              // 0..1023
        int n = g >> 4;                     // k_out 0..63
        int u = g & 15;                     // 16B unit 0..15
        uint32_t doff = (uint32_t)(n * (LDA * 2) + u * 16);
        const __nv_bfloat16* srch = g_Mhi + (size_t)n * 1024 + ch * CHUNK + u * 8;
        const __nv_bfloat16* srcl = g_Mlo + (size_t)n * 1024 + ch * CHUNK + u * 8;
        CP_ASYNC16(sh + doff, srch);
        CP_ASYNC16(sl + doff, srcl);
    }
}

__device__ __forceinline__ void sts_a(char* stage, int tid, const float4 pa[8]) {
#pragma unroll
    for (int t = 0; t < 8; t++) {
        int g = tid + t * 256;
        int r = g >> 5;
        int c4 = (g & 31) * 4;
        uint32_t h0, l0, h1, l1;
        split_pair(pa[t].x, pa[t].y, h0, l0);
        split_pair(pa[t].z, pa[t].w, h1, l1);
        int off = (r * LDA + c4) * 2;
        *reinterpret_cast<uint2*>(stage + A_HI + off) = make_uint2(h0, h1);
        *reinterpret_cast<uint2*>(stage + A_LO + off) = make_uint2(l0, l1);
    }
}

// Warp tile 16m x 32n; fragments via ldmatrix.x4; 3-term split-bf16 MMA.
__device__ __forceinline__ void compute_chunk(uint32_t st, int m0, int nb,
                                              int lane, float d[4][4]) {
    // A lanes: tile order (m0-7,k0),(m8-15,k0),(m0-7,k8),(m8-15,k8)
    int arow = m0 + (lane & 15);
    int acol = (lane >> 4) << 3;                 // 0 or 8
    // B lanes: tile order (n0-7,k0),(n0-7,k8),(n8-15,k0),(n8-15,k8)
    int nrow = (lane & 7) + ((lane & 16) >> 1);  // 0..15
    int bcol = lane & 8;                         // 0 or 8
    uint32_t ah = st + A_HI + (uint32_t)(arow * LDA + acol) * 2;
    uint32_t al = st + A_LO + (uint32_t)(arow * LDA + acol) * 2;
    uint32_t ph = st + B_HI + (uint32_t)((nb + nrow) * LDA + bcol) * 2;
    uint32_t pl = st + B_LO + (uint32_t)((nb + nrow) * LDA + bcol) * 2;
    const uint32_t nstep = 16u * LDA * 2u;       // n16 group stride

#pragma unroll
    for (int ks = 0; ks < CHUNK / 16; ks++) {
        uint32_t koff = (uint32_t)ks * 32;
        uint32_t A[4], C[4];
        uint32_t p0, p1, p2, p3, q0, q1, q2, q3;
        uint32_t r0, r1, r2, r3, s0, s1, s2, s3;
        LDSM4(A[0], A[1], A[2], A[3], ah + koff);           // A hi (m16k16)
        LDSM4(C[0], C[1], C[2], C[3], al + koff);           // A lo
        LDSM4(p0, p1, p2, p3, ph + koff);                   // B hi n[0:16)
        LDSM4(q0, q1, q2, q3, ph + nstep + koff);           // B hi n[16:32)
        LDSM4(r0, r1, r2, r3, pl + koff);                   // B lo n[0:16)
        LDSM4(s0, s1, s2, s3, pl + nstep + koff);           // B lo n[16:32)
        // 4 independent accumulator chains, 3 deep (hh, hl, lh)
        mma16816(d[0], A, p0, p1);
        mma16816(d[1], A, p2, p3);
        mma16816(d[2], A, q0, q1);
        mma16816(d[3], A, q2, q3);
        mma16816(d[0], A, r0, r1);
        mma16816(d[1], A, r2, r3);
        mma16816(d[2], A, s0, s1);
        mma16816(d[3], A, s2, s3);
        mma16816(d[0], C, p0, p1);
        mma16816(d[1], C, p2, p3);
        mma16816(d[2], C, q0, q1);
        mma16816(d[3], C, q2, q3);
    }
}

__global__ __launch_bounds__(256, 1) void gemm_mma(const float* __restrict__ x1,
                                                   const float* __restrict__ U,
                                                   float* __restrict__ out) {
    extern __shared__ char smem[];
    int tid = threadIdx.x, lane = tid & 31, wid = tid >> 5;
    int wr = wid & 3, wc = wid >> 2;
    int m0 = wr * 16, nb = wc * 32;
    int row0 = blockIdx.x * 64;

    float* sc = reinterpret_cast<float*>(smem + C_OFF);
    float* su = reinterpret_cast<float*>(smem + U_OFF);
    float* red = reinterpret_cast<float*>(smem + RED_OFF);
    if (tid < 64) {
        sc[tid] = g_c[tid];
        su[tid] = U[tid];
    }

    float d[4][4] = {};
    float4 pa[8];

    ldg_a(x1, row0, 0, tid, pa);
    cpasync_b(smem, 0, tid);
    CP_COMMIT();
    sts_a(smem, tid, pa);
    CP_WAIT0();
    __syncthreads();

    for (int ch = 0; ch < 8; ch++) {
        char* cur = smem + (ch & 1) * STAGE_BYTES;
        char* nxt = smem + ((ch + 1) & 1) * STAGE_BYTES;
        if (ch < 7) {
            ldg_a(x1, row0, ch + 1, tid, pa);    // LDGs fly during compute
            cpasync_b(nxt, ch + 1, tid);
            CP_COMMIT();
        }
        compute_chunk(smem_u32(cur), m0, nb, lane, d);
        if (ch < 7) {
            sts_a(nxt, tid, pa);
            CP_WAIT0();
            __syncthreads();
        }
    }

    // fused epilogue: relu(D + c)*U, row-reduce over 64 cols -> out (N,1)
    int g = lane >> 2, tg2 = (lane & 3) * 2;
    float accA = 0.0f, accB = 0.0f;
#pragma unroll
    for (int j = 0; j < 4; j++) {
        int col = nb + j * 8 + tg2;
        float c0 = sc[col], c1 = sc[col + 1];
        float u0 = su[col], u1 = su[col + 1];
        accA += fmaxf(d[j][0] + c0, 0.0f) * u0 + fmaxf(d[j][1] + c1, 0.0f) * u1;
        accB += fmaxf(d[j][2] + c0, 0.0f) * u0 + fmaxf(d[j][3] + c1, 0.0f) * u1;
    }
    accA += __shfl_xor_sync(0xFFFFFFFFu, accA, 1);
    accA += __shfl_xor_sync(0xFFFFFFFFu, accA, 2);
    accB += __shfl_xor_sync(0xFFFFFFFFu, accB, 1);
    accB += __shfl_xor_sync(0xFFFFFFFFu, accB, 2);
    if ((lane & 3) == 0) {
        red[wc * 64 + m0 + g] = accA;
        red[wc * 64 + m0 + 8 + g] = accB;
    }
    __syncthreads();
    if (tid < 64) out[row0 + tid] = red[tid] + red[64 + tid];
}

// ---------------------------------------------------------------------------
extern "C" void kernel_launch(void* const* d_in, const int* in_sizes, int n_in,
                              void* d_out, int out_size) {
    const float* x1 = (const float*)d_in[0];  // (8192, 1024)
    const float* x2 = (const float*)d_in[1];  // (1, 1024)
    const float* V  = (const float*)d_in[2];  // (64, 2048)
    const float* W  = (const float*)d_in[3];  // (64, 1024, 1024)
    const float* b  = (const float*)d_in[4];  // (64,)
    const float* U  = (const float*)d_in[5];  // (64, 1)
    float* out = (float*)d_out;               // (8192, 1)

    cudaFuncSetAttribute(gemm_mma, cudaFuncAttributeMaxDynamicSharedMemorySize, SMEM_TOTAL);

    wx2_kernel<<<8192 + 64, 256>>>(W, V, x2, b);     // HBM-bound + fused c blocks
    gemm_mma<<<128, 256, SMEM_TOTAL>>>(x1, U, out);  // ldmatrix+cp.async HMMA GEMM
}